// round 2
// baseline (speedup 1.0000x reference)
#include <cuda_runtime.h>
#include <cuda_bf16.h>
#include <math.h>

// Problem constants
#define NTOK   65536      // 64 * 32 * 32 tokens
#define DIM    256
#define KCODE  1024
#define HW     1024       // 32*32 tokens per batch image

// GEMM-argmin tiling
#define BM 128
#define BN 128
#define DK 16
#define TM 8
#define TN 8

// Scratch (no cudaMalloc allowed)
__device__ float  g_cnorm[KCODE];
__device__ int    g_idx[NTOK];
__device__ int    g_counts[KCODE];
__device__ double g_loss;

// ---------------------------------------------------------------------------
// Kernel A: codebook norms (SEQUENTIAL fp32, no-FMA to mirror XLA's reduce)
// + zero accumulators.  4 blocks x 256 threads = 1024 threads, 1 per code.
// ---------------------------------------------------------------------------
__global__ void prep_kernel(const float* __restrict__ cb) {
    int gid = blockIdx.x * blockDim.x + threadIdx.x;
    if (gid < KCODE) {
        const float* row = cb + (size_t)gid * DIM;
        float s = 0.f;
        for (int d = 0; d < DIM; d++) {
            float v = row[d];
            s = __fadd_rn(s, __fmul_rn(v, v));   // RN(x*x) then RN add, in order
        }
        g_cnorm[gid] = s;
        g_counts[gid] = 0;
    }
    if (gid == 0) g_loss = 0.0;
}

// ---------------------------------------------------------------------------
// Kernel B: fused GEMM + argmin + loss + histogram.
// Block = 256 threads handles BM=128 tokens vs all K=1024 codes.
// Score replicates the reference bit-rounding:
//   s = RN( RN(xn + cn) - RN(2 * dot) )
// with dot accumulated as a single fp32 FMA chain over k = 0..255 ascending
// (Eigen gebp order), and xn the sequential no-FMA fp32 sum of x_d^2.
// ---------------------------------------------------------------------------
__global__ __launch_bounds__(256)
void argmin_kernel(const float* __restrict__ x, const float* __restrict__ cb,
                   float* __restrict__ out_idx_f) {
    __shared__ float As[DK][BM + 4];
    __shared__ float Bs[DK][BN + 4];
    __shared__ float s_xnorm[BM];
    __shared__ float s_candv[BM][17];
    __shared__ int   s_candi[BM][17];
    __shared__ float s_red[256];

    const int tid  = threadIdx.x;
    const int t0   = blockIdx.x * BM;      // global token start
    const int b    = t0 >> 10;             // batch index
    const int tloc = t0 & (HW - 1);        // token within batch image
    const float* xb = x + (size_t)b * DIM * HW + tloc;  // element (d,m) at xb[d*HW + m]

    // --- prologue: sequential fp32 ||x||^2 per token (XLA reduce order) ---
    if (tid < BM) {
        const float* xp = xb + tid;
        float s = 0.f;
        #pragma unroll 8
        for (int d = 0; d < DIM; d++) {
            float v = xp[(size_t)d * HW];
            s = __fadd_rn(s, __fmul_rn(v, v));
        }
        s_xnorm[tid] = s;
    }
    __syncthreads();

    const int tm = tid & 15;               // token-tile coord (16)
    const int tn = tid >> 4;               // code-tile coord (16)

    float xr[TM];
    #pragma unroll
    for (int i = 0; i < TM; i++) xr[i] = s_xnorm[tm * TM + i];

    float minv[TM];
    int   mini[TM];
    #pragma unroll
    for (int i = 0; i < TM; i++) { minv[i] = INFINITY; mini[i] = 0; }

    for (int nc = 0; nc < KCODE / BN; nc++) {
        const int cb0 = nc * BN;
        float acc[TM][TN];
        #pragma unroll
        for (int i = 0; i < TM; i++)
            #pragma unroll
            for (int j = 0; j < TN; j++) acc[i][j] = 0.f;

        for (int ds = 0; ds < DIM / DK; ds++) {
            const int d0 = ds * DK;
            // Load A tile [DK x BM]: contiguous in m -> coalesced 512B rows.
            #pragma unroll
            for (int j = 0; j < 8; j++) {
                int i = tid + 256 * j;
                int k = i >> 7, m = i & 127;
                As[k][m] = xb[(size_t)(d0 + k) * HW + m];
            }
            // Load B tile transposed [DK x BN] from codebook rows (L2 hot).
            #pragma unroll
            for (int j = 0; j < 8; j++) {
                int i = tid + 256 * j;
                int k = i & 15, n = i >> 4;
                Bs[k][n] = cb[(size_t)(cb0 + n) * DIM + d0 + k];
            }
            __syncthreads();

            // k strictly ascending, single fp32 accumulator, FMA -> Eigen order
            #pragma unroll
            for (int k = 0; k < DK; k++) {
                float a[TM], bb[TN];
                #pragma unroll
                for (int i = 0; i < TM; i++) a[i] = As[k][tm * TM + i];
                #pragma unroll
                for (int j = 0; j < TN; j++) bb[j] = Bs[k][tn * TN + j];
                #pragma unroll
                for (int i = 0; i < TM; i++)
                    #pragma unroll
                    for (int j = 0; j < TN; j++)
                        acc[i][j] = __fmaf_rn(a[i], bb[j], acc[i][j]);
            }
            __syncthreads();
        }

        // fold chunk scores into running per-thread argmin with the exact
        // reference rounding: RN( RN(xn+cn) - RN(2*dot) )
        #pragma unroll
        for (int j = 0; j < TN; j++) {
            int n = cb0 + tn * TN + j;
            float cn = __ldg(&g_cnorm[n]);
            #pragma unroll
            for (int i = 0; i < TM; i++) {
                float t1 = __fadd_rn(xr[i], cn);
                float s  = __fadd_rn(t1, __fmul_rn(-2.f, acc[i][j]));
                if (s < minv[i]) { minv[i] = s; mini[i] = n; }  // strict: first wins
            }
        }
    }

    // cross-thread (tn) argmin reduction per token, lowest index on ties
    #pragma unroll
    for (int i = 0; i < TM; i++) {
        s_candv[tm * TM + i][tn] = minv[i];
        s_candi[tm * TM + i][tn] = mini[i];
    }
    __syncthreads();

    float tok_loss = 0.f;
    if (tid < BM) {
        float bv = s_candv[tid][0];
        int   bi = s_candi[tid][0];
        #pragma unroll
        for (int t = 1; t < 16; t++) {
            float v  = s_candv[tid][t];
            int   ii = s_candi[tid][t];
            if (v < bv || (v == bv && ii < bi)) { bv = v; bi = ii; }
        }
        int gt = t0 + tid;
        g_idx[gt] = bi;
        out_idx_f[gt] = (float)bi;
        atomicAdd(&g_counts[bi], 1);
        tok_loss = bv;   // bv = xn + cn - 2*dot = sum_d (q_d - x_d)^2
    }

    // block reduce tok_loss -> double accumulator
    s_red[tid] = tok_loss;
    __syncthreads();
    #pragma unroll
    for (int s = 128; s > 0; s >>= 1) {
        if (tid < s) s_red[tid] += s_red[tid + s];
        __syncthreads();
    }
    if (tid == 0) atomicAdd(&g_loss, (double)s_red[0]);
}

// ---------------------------------------------------------------------------
// Kernel C: gather quantized rows and write NCHW output, staged via SMEM
// so codebook reads are row-contiguous and NCHW stores are coalesced.
// ---------------------------------------------------------------------------
#define CD 64
__global__ __launch_bounds__(256)
void gather_kernel(const float* __restrict__ cb, float* __restrict__ out_q) {
    __shared__ float qs[BM][CD + 1];
    __shared__ int   sidx[BM];
    const int tid  = threadIdx.x;
    const int t0   = blockIdx.x * BM;
    const int b    = t0 >> 10;
    const int tloc = t0 & (HW - 1);
    float* ob = out_q + (size_t)b * DIM * HW + tloc;

    if (tid < BM) sidx[tid] = g_idx[t0 + tid];
    __syncthreads();

    const int m    = tid >> 1;          // token row this thread gathers
    const int part = (tid & 1) * 32;    // which half of the 64-wide chunk

    for (int d0 = 0; d0 < DIM; d0 += CD) {
        const float4* src =
            (const float4*)(cb + (size_t)sidx[m] * DIM + d0 + part);
        #pragma unroll
        for (int q = 0; q < 8; q++) {
            float4 v = src[q];
            int dd = part + q * 4;
            qs[m][dd + 0] = v.x; qs[m][dd + 1] = v.y;
            qs[m][dd + 2] = v.z; qs[m][dd + 3] = v.w;
        }
        __syncthreads();
        #pragma unroll
        for (int j = 0; j < (BM * CD) / 256; j++) {
            int i = tid + 256 * j;
            int d = i >> 7, mm = i & 127;
            ob[(size_t)(d0 + d) * HW + mm] = qs[mm][d];
        }
        __syncthreads();
    }
}

// ---------------------------------------------------------------------------
// Kernel D: finalize loss + perplexity. 1 block x 1024 threads.
// ---------------------------------------------------------------------------
__global__ void finalize_kernel(float* __restrict__ out_loss,
                                float* __restrict__ out_perp) {
    __shared__ double sred[KCODE];
    int t = threadIdx.x;
    double p = (double)g_counts[t] / (double)NTOK;
    sred[t] = p * log(p + 1e-10);
    __syncthreads();
    #pragma unroll
    for (int s = 512; s > 0; s >>= 1) {
        if (t < s) sred[t] += sred[t + s];
        __syncthreads();
    }
    if (t == 0) {
        out_perp[0] = (float)exp(-sred[0]);
        // loss = q_latent + 0.25 * e_latent, both equal mean((q-x)^2)
        out_loss[0] = (float)(1.25 * g_loss / ((double)NTOK * (double)DIM));
    }
}

// ---------------------------------------------------------------------------
// Launch: outputs concatenated in tuple order as float32:
//   [loss(1) | quantized_ste NCHW (4194304) | perplexity(1) | idx(65536)]
// ---------------------------------------------------------------------------
extern "C" void kernel_launch(void* const* d_in, const int* in_sizes, int n_in,
                              void* d_out, int out_size) {
    const float* x  = (const float*)d_in[0];
    const float* cb = (const float*)d_in[1];
    // defensive: identify by size (inputs = 4194304 elems, codebook = 262144)
    if (n_in >= 2 && in_sizes[0] < in_sizes[1]) {
        const float* t = x; x = cb; cb = t;
    }

    float* out      = (float*)d_out;
    float* out_loss = out;
    float* out_q    = out + 1;
    float* out_perp = out + 1 + (size_t)NTOK * DIM;
    float* out_idx  = out + 2 + (size_t)NTOK * DIM;

    prep_kernel   <<<4, 256>>>(cb);
    argmin_kernel <<<NTOK / BM, 256>>>(x, cb, out_idx);
    gather_kernel <<<NTOK / BM, 256>>>(cb, out_q);
    finalize_kernel<<<1, KCODE>>>(out_loss, out_perp);
}

// round 6
// speedup vs baseline: 4.0815x; 4.0815x over previous
#include <cuda_runtime.h>
#include <math.h>
#include <stdint.h>

// Problem constants
#define NTOK   65536
#define DIM    256
#define KCODE  1024
#define HW     1024
#define MT     256          // tokens per CTA
#define NC     64           // codes per B chunk
#define CHUNKS 16
#define MARGIN 8.0e-4f
#define APAD   132          // u32 (bf16x2) per A row (128 + 4 pad)
#define BPAD   132          // u32 (bf16x2) per B row (128 + 4 pad)

// smem byte offsets
#define OFF_A     0                             // 256*132*4 = 135168
#define OFF_B     135168                        // 2*64*132*4 = 67584
#define OFF_CN    202752                        // 1024 f32
#define OFF_CANDV 206848                        // 256*8 f32
#define OFF_CANDI 215040                        // 256*8 i32
#define OFF_THR   223232                        // 256 u32
#define OFF_CNT   224256                        // 256 u32
#define OFF_XN    225280                        // 256 f32
#define OFF_RED   226304                        // 256 f32
#define SMEM_TOTAL 227328

__device__ __align__(16) float    g_cnorm[KCODE];
__device__ __align__(16) uint32_t g_cbf[KCODE * DIM / 2];   // bf16 codebook
__device__ int    g_idx[NTOK];
__device__ int    g_counts[KCODE];
__device__ double g_loss;

// ---------------- helpers ----------------
__device__ __forceinline__ uint32_t smem_u32(const void* p) {
    uint32_t a;
    asm("{ .reg .u64 t; cvta.to.shared.u64 t, %1; cvt.u32.u64 %0, t; }" : "=r"(a) : "l"(p));
    return a;
}
__device__ __forceinline__ uint32_t fkey(float f) {
    uint32_t u = __float_as_uint(f);
    return u ^ (uint32_t)(((int32_t)u >> 31) | 0x80000000);
}
__device__ __forceinline__ float fdec(uint32_t k) {
    uint32_t u = (k & 0x80000000u) ? (k ^ 0x80000000u) : ~k;
    return __uint_as_float(u);
}
__device__ __forceinline__ uint32_t packbf(float lo, float hi) {
    uint32_t r;
    asm("cvt.rn.bf16x2.f32 %0, %1, %2;" : "=r"(r) : "f"(hi), "f"(lo));
    return r;
}
__device__ __forceinline__ void mma_bf16(float* c, uint32_t a0, uint32_t a1,
                                         uint32_t a2, uint32_t a3,
                                         uint32_t b0, uint32_t b1) {
    asm volatile("mma.sync.aligned.m16n8k16.row.col.f32.bf16.bf16.f32 "
                 "{%0,%1,%2,%3}, {%4,%5,%6,%7}, {%8,%9}, {%0,%1,%2,%3};"
                 : "+f"(c[0]), "+f"(c[1]), "+f"(c[2]), "+f"(c[3])
                 : "r"(a0), "r"(a1), "r"(a2), "r"(a3), "r"(b0), "r"(b1));
}
__device__ __forceinline__ void cp_async16(uint32_t dst, const void* src) {
    asm volatile("cp.async.cg.shared.global [%0], [%1], 16;"
                 :: "r"(dst), "l"(__cvta_generic_to_global(src)) : "memory");
}
#define CP_COMMIT() asm volatile("cp.async.commit_group;" ::: "memory")
#define CP_WAIT1()  asm volatile("cp.async.wait_group 1;" ::: "memory")
#define CP_WAIT0()  asm volatile("cp.async.wait_group 0;" ::: "memory")

// ---------------------------------------------------------------------------
// Kernel A: sequential fp32 codebook norms (bit-identical to ref reduce) +
// bf16 codebook conversion + zero accumulators.
// ---------------------------------------------------------------------------
__global__ void prep_kernel(const float* __restrict__ cb) {
    int gid = blockIdx.x * blockDim.x + threadIdx.x;
    if (gid < KCODE) {
        const float4* row = (const float4*)(cb + (size_t)gid * DIM);
        uint32_t* dst = g_cbf + (size_t)gid * (DIM / 2);
        float s = 0.f;
        #pragma unroll 4
        for (int q = 0; q < DIM / 4; q++) {
            float4 v = row[q];
            s = __fadd_rn(s, __fmul_rn(v.x, v.x));
            s = __fadd_rn(s, __fmul_rn(v.y, v.y));
            s = __fadd_rn(s, __fmul_rn(v.z, v.z));
            s = __fadd_rn(s, __fmul_rn(v.w, v.w));
            dst[2 * q]     = packbf(v.x, v.y);
            dst[2 * q + 1] = packbf(v.z, v.w);
        }
        g_cnorm[gid] = s;
        g_counts[gid] = 0;
    }
    if (gid == 0) g_loss = 0.0;
}

// ---------------------------------------------------------------------------
// Main fused kernel: bf16 mma.sync scoring + register candidate rings +
// exact fp32 rescue + argmin + histogram + loss.  256 CTAs x 256 threads.
// ---------------------------------------------------------------------------
__global__ __launch_bounds__(256, 1)
void argmin_kernel(const float* __restrict__ x, const float* __restrict__ cb,
                   float* __restrict__ out_idx_f) {
    extern __shared__ char smem[];
    uint32_t* Au    = (uint32_t*)(smem + OFF_A);
    uint32_t* Bu0   = (uint32_t*)(smem + OFF_B);
    float*    cnS   = (float*)(smem + OFF_CN);
    float*    candv = (float*)(smem + OFF_CANDV);
    int*      candi = (int*)(smem + OFF_CANDI);
    uint32_t* thrS  = (uint32_t*)(smem + OFF_THR);
    uint32_t* cntS  = (uint32_t*)(smem + OFF_CNT);
    float*    xnS   = (float*)(smem + OFF_XN);
    float*    redS  = (float*)(smem + OFF_RED);

    const uint32_t sbB = smem_u32(smem + OFF_B);

    const int tid  = threadIdx.x;
    const int lane = tid & 31;
    const int wid  = tid >> 5;
    const int g    = lane >> 2;
    const int t    = lane & 3;

    const int t0   = blockIdx.x * MT;
    const int b    = t0 >> 10;
    const int tloc = t0 & (HW - 1);
    const float* xb = x + (size_t)b * DIM * HW + tloc;   // (d,m): xb[d*HW+m]

    // ---- issue B chunk 0 cp.async (overlaps A pass) ----
    {
        #pragma unroll
        for (int it = 0; it < 8; it++) {
            int e = tid + 256 * it;               // 0..2047
            int n = e >> 5, s4 = e & 31;          // 64 rows x 32 x 16B = full 32KB
            cp_async16(sbB + (uint32_t)(n * (BPAD * 4) + s4 * 16),
                       g_cbf + (size_t)n * (DIM / 2) + s4 * 4);
        }
        CP_COMMIT();
    }

    // ---- per-token init ----
    thrS[tid] = 0xFF800000u;    // fkey(+inf)
    cntS[tid] = 0;
    ((float4*)cnS)[tid] = ((const float4*)g_cnorm)[tid];

    // ---- A pass: exact sequential xn + bf16 A tile ----
    {
        const float* xp = xb + tid;               // token m = tid
        float xn = 0.f, prev = 0.f;
        #pragma unroll 8
        for (int d = 0; d < DIM; d++) {
            float v = xp[(size_t)d * HW];
            xn = __fadd_rn(xn, __fmul_rn(v, v));
            if (d & 1) Au[tid * APAD + (d >> 1)] = packbf(prev, v);
            else prev = v;
        }
        xnS[tid] = xn;
    }
    __syncthreads();

    // ---- MMA setup ----
    const int warpM = wid;                        // rows warpM*32 .. +31
    uint32_t* Ap = Au + (warpM * 32 + g) * APAD + t;
    const int rowbase = warpM * 32 + g;           // rows rowbase + 8*ri, ri=0..3

    float acc[2][8][4];
    // per-(thread,row) candidate shift-rings (4 newest within margin of local min)
    float lmin0 = INFINITY, lmin1 = INFINITY, lmin2 = INFINITY, lmin3 = INFINITY;
    float rv0[4], rv1[4], rv2[4], rv3[4];
    int   ri0[4], ri1[4], ri2[4], ri3[4];
    int   rc0 = 0, rc1 = 0, rc2 = 0, rc3 = 0;

#define RING_PUSH(RV, RI, RC, LM, sval, nval)                      \
    do {                                                           \
        if ((sval) < (LM) + MARGIN) {                              \
            RV[3] = RV[2]; RI[3] = RI[2];                          \
            RV[2] = RV[1]; RI[2] = RI[1];                          \
            RV[1] = RV[0]; RI[1] = RI[0];                          \
            RV[0] = (sval); RI[0] = (nval); RC++;                  \
            if ((sval) < (LM)) (LM) = (sval);                      \
        }                                                          \
    } while (0)

    for (int c = 0; c < CHUNKS; c++) {
        // issue chunk c+1 into the other buffer
        if (c + 1 < CHUNKS) {
            const uint32_t base = sbB + (uint32_t)(((c + 1) & 1) * (NC * BPAD * 4));
            const uint32_t* srcb = g_cbf + (size_t)(c + 1) * NC * (DIM / 2);
            #pragma unroll
            for (int it = 0; it < 8; it++) {
                int e = tid + 256 * it;
                int n = e >> 5, s4 = e & 31;
                cp_async16(base + (uint32_t)(n * (BPAD * 4) + s4 * 16),
                           srcb + (size_t)n * (DIM / 2) + s4 * 4);
            }
        }
        CP_COMMIT();
        if (c + 1 < CHUNKS) CP_WAIT1(); else CP_WAIT0();
        __syncthreads();                          // chunk c visible to all warps

        #pragma unroll
        for (int i = 0; i < 2; i++)
            #pragma unroll
            for (int j = 0; j < 8; j++)
                #pragma unroll
                for (int e = 0; e < 4; e++) acc[i][j][e] = 0.f;

        uint32_t* Br = Bu0 + (c & 1) * (NC * BPAD) + g * BPAD + t;

        #pragma unroll
        for (int ks = 0; ks < 16; ks++) {
            const int col = ks * 8;               // u32 column
            uint32_t a0 = Ap[col],                 a1 = Ap[8 * APAD + col];
            uint32_t a2 = Ap[col + 4],             a3 = Ap[8 * APAD + col + 4];
            uint32_t a4 = Ap[16 * APAD + col],     a5 = Ap[24 * APAD + col];
            uint32_t a6 = Ap[16 * APAD + col + 4], a7 = Ap[24 * APAD + col + 4];
            #pragma unroll
            for (int j = 0; j < 8; j++) {
                uint32_t b0 = Br[j * 8 * BPAD + col];
                uint32_t b1 = Br[j * 8 * BPAD + col + 4];
                mma_bf16(acc[0][j], a0, a1, a2, a3, b0, b1);
                mma_bf16(acc[1][j], a4, a5, a6, a7, b0, b1);
            }
        }

        // fold chunk scores into register rings
        const int cb0 = c * NC;
        #pragma unroll
        for (int j = 0; j < 8; j++) {
            int n0 = cb0 + j * 8 + 2 * t;
            float cn0 = cnS[n0], cn1 = cnS[n0 + 1];
            {   // i=0: rows rowbase (e0,e1), rowbase+8 (e2,e3)
                float s00 = fmaf(-2.f, acc[0][j][0], cn0);
                float s01 = fmaf(-2.f, acc[0][j][1], cn1);
                float s10 = fmaf(-2.f, acc[0][j][2], cn0);
                float s11 = fmaf(-2.f, acc[0][j][3], cn1);
                RING_PUSH(rv0, ri0, rc0, lmin0, s00, n0);
                RING_PUSH(rv0, ri0, rc0, lmin0, s01, n0 + 1);
                RING_PUSH(rv1, ri1, rc1, lmin1, s10, n0);
                RING_PUSH(rv1, ri1, rc1, lmin1, s11, n0 + 1);
            }
            {   // i=1: rows rowbase+16, rowbase+24
                float s00 = fmaf(-2.f, acc[1][j][0], cn0);
                float s01 = fmaf(-2.f, acc[1][j][1], cn1);
                float s10 = fmaf(-2.f, acc[1][j][2], cn0);
                float s11 = fmaf(-2.f, acc[1][j][3], cn1);
                RING_PUSH(rv2, ri2, rc2, lmin2, s00, n0);
                RING_PUSH(rv2, ri2, rc2, lmin2, s01, n0 + 1);
                RING_PUSH(rv3, ri3, rc3, lmin3, s10, n0);
                RING_PUSH(rv3, ri3, rc3, lmin3, s11, n0 + 1);
            }
        }
        __syncthreads();                          // all reads of buf c&1 done
    }

    // ---- merge: global per-row threshold ----
    atomicMin(&thrS[rowbase],      fkey(lmin0));
    atomicMin(&thrS[rowbase + 8],  fkey(lmin1));
    atomicMin(&thrS[rowbase + 16], fkey(lmin2));
    atomicMin(&thrS[rowbase + 24], fkey(lmin3));
    __syncthreads();

    // ---- filter-write candidates within gmin+MARGIN to shared (<= 8/token) ----
#define FILTER_ROW(RV, RI, RC, ROW)                                          \
    do {                                                                     \
        float thr = fdec(thrS[ROW]) + MARGIN;                                \
        int k = (RC < 4) ? RC : 4;                                           \
        _Pragma("unroll")                                                    \
        for (int sl = 0; sl < 4; sl++) {                                     \
            if (sl < k && RV[sl] <= thr) {                                   \
                uint32_t old = atomicAdd(&cntS[ROW], 1u);                    \
                if (old < 8) {                                               \
                    candv[(ROW) * 8 + old] = RV[sl];                         \
                    candi[(ROW) * 8 + old] = RI[sl];                         \
                }                                                            \
            }                                                                \
        }                                                                    \
    } while (0)
    FILTER_ROW(rv0, ri0, rc0, rowbase);
    FILTER_ROW(rv1, ri1, rc1, rowbase + 8);
    FILTER_ROW(rv2, ri2, rc2, rowbase + 16);
    FILTER_ROW(rv3, ri3, rc3, rowbase + 24);
    __syncthreads();

    // ---- final per-token selection + exact rescue (token m = tid) ----
    float tok_loss = 0.f;
    int   bei = 0;
    {
        const int m = tid;
        const float xn = xnS[m];
        uint32_t nv = cntS[m]; if (nv > 8) nv = 8;

        if (nv == 1) {
            bei = candi[m * 8];
            tok_loss = __fadd_rn(xn, candv[m * 8]);
        } else if (nv >= 2) {
            float bev = __int_as_float(0x7F800000);
            bei = 0x7fffffff;
            for (int base = 0; base < 8; base += 4) {
                if (base >= (int)nv) break;
                bool val[4]; int nn[4];
                #pragma unroll
                for (int q = 0; q < 4; q++) {
                    int sl = base + q;
                    bool v = (sl < (int)nv);
                    val[q] = v;
                    nn[q] = v ? candi[m * 8 + sl] : 0;
                }
                const float* p0 = cb + (size_t)nn[0] * DIM;
                const float* p1 = cb + (size_t)nn[1] * DIM;
                const float* p2 = cb + (size_t)nn[2] * DIM;
                const float* p3 = cb + (size_t)nn[3] * DIM;
                float a0 = 0.f, a1 = 0.f, a2 = 0.f, a3 = 0.f;
                #pragma unroll 8
                for (int d = 0; d < DIM; d++) {
                    float a = xb[(size_t)d * HW + m];    // exact f32 x
                    a0 = __fmaf_rn(a, p0[d], a0);
                    a1 = __fmaf_rn(a, p1[d], a1);
                    a2 = __fmaf_rn(a, p2[d], a2);
                    a3 = __fmaf_rn(a, p3[d], a3);
                }
                float accs[4] = {a0, a1, a2, a3};
                #pragma unroll
                for (int q = 0; q < 4; q++) {
                    if (!val[q]) continue;
                    float cn = cnS[nn[q]];
                    float t1 = __fadd_rn(xn, cn);
                    float se = __fadd_rn(t1, __fmul_rn(-2.f, accs[q]));
                    if (se < bev || (se == bev && nn[q] < bei)) { bev = se; bei = nn[q]; }
                }
            }
            tok_loss = bev;
        }
        // nv == 0 is impossible (global-min achiever always survives); guard = 0 loss

        int gt = t0 + m;
        g_idx[gt] = bei;
        out_idx_f[gt] = (float)bei;
        atomicAdd(&g_counts[bei], 1);
    }

    // ---- block loss reduction ----
    redS[tid] = tok_loss;
    __syncthreads();
    #pragma unroll
    for (int s = 128; s > 0; s >>= 1) {
        if (tid < s) redS[tid] += redS[tid + s];
        __syncthreads();
    }
    if (tid == 0) atomicAdd(&g_loss, (double)redS[0]);
}

// ---------------------------------------------------------------------------
// Gather quantized rows -> NCHW output (SMEM staged, fully coalesced)
// ---------------------------------------------------------------------------
#define GMT 128
#define CD  64
__global__ __launch_bounds__(256)
void gather_kernel(const float* __restrict__ cb, float* __restrict__ out_q) {
    __shared__ float qs[GMT][CD + 1];
    __shared__ int   sidx[GMT];
    const int tid  = threadIdx.x;
    const int t0   = blockIdx.x * GMT;
    const int b    = t0 >> 10;
    const int tloc = t0 & (HW - 1);
    float* ob = out_q + (size_t)b * DIM * HW + tloc;

    if (tid < GMT) sidx[tid] = g_idx[t0 + tid];
    __syncthreads();

    const int mm   = tid >> 1;
    const int part = (tid & 1) * 32;

    for (int d0 = 0; d0 < DIM; d0 += CD) {
        const float4* src = (const float4*)(cb + (size_t)sidx[mm] * DIM + d0 + part);
        #pragma unroll
        for (int q = 0; q < 8; q++) {
            float4 v = src[q];
            int dd = part + q * 4;
            qs[mm][dd + 0] = v.x; qs[mm][dd + 1] = v.y;
            qs[mm][dd + 2] = v.z; qs[mm][dd + 3] = v.w;
        }
        __syncthreads();
        #pragma unroll
        for (int j = 0; j < (GMT * CD) / 256; j++) {
            int i = tid + 256 * j;
            int d = i >> 7, m2 = i & 127;
            ob[(size_t)(d0 + d) * HW + m2] = qs[m2][d];
        }
        __syncthreads();
    }
}

// ---------------------------------------------------------------------------
// Finalize: loss + perplexity
// ---------------------------------------------------------------------------
__global__ void finalize_kernel(float* __restrict__ out_loss,
                                float* __restrict__ out_perp) {
    __shared__ float sred[KCODE];
    int t = threadIdx.x;
    float p = (float)g_counts[t] / (float)NTOK;
    sred[t] = p * logf(p + 1e-10f);
    __syncthreads();
    #pragma unroll
    for (int s = 512; s > 0; s >>= 1) {
        if (t < s) sred[t] += sred[t + s];
        __syncthreads();
    }
    if (t == 0) {
        out_perp[0] = expf(-sred[0]);
        out_loss[0] = (float)(1.25 * g_loss / ((double)NTOK * (double)DIM));
    }
}

// ---------------------------------------------------------------------------
extern "C" void kernel_launch(void* const* d_in, const int* in_sizes, int n_in,
                              void* d_out, int out_size) {
    const float* x  = (const float*)d_in[0];
    const float* cb = (const float*)d_in[1];
    if (n_in >= 2 && in_sizes[0] < in_sizes[1]) {
        const float* t = x; x = cb; cb = t;
    }

    float* out      = (float*)d_out;
    float* out_loss = out;
    float* out_q    = out + 1;
    float* out_perp = out + 1 + (size_t)NTOK * DIM;
    float* out_idx  = out + 2 + (size_t)NTOK * DIM;

    static int attr_done = 0;
    if (!attr_done) {
        cudaFuncSetAttribute(argmin_kernel, cudaFuncAttributeMaxDynamicSharedMemorySize, SMEM_TOTAL);
        attr_done = 1;
    }

    prep_kernel   <<<4, 256>>>(cb);
    argmin_kernel <<<NTOK / MT, 256, SMEM_TOTAL>>>(x, cb, out_idx);
    gather_kernel <<<NTOK / GMT, 256>>>(cb, out_q);
    finalize_kernel<<<1, KCODE>>>(out_loss, out_perp);
}